// round 2
// baseline (speedup 1.0000x reference)
#include <cuda_runtime.h>
#include <cstdint>

#define N_PTS 100000
#define KNN   16
#define CIN   64
#define CMID  64
#define COUT  128
#define NK    (N_PTS * KNN)
#define EPSB  1e-5f

// ---------------- scratch (static device memory; no dynamic alloc) ----------
__device__ int   g_counts[N_PTS];
__device__ float g_y1[(size_t)N_PTS * CMID];   // pre-BN layer-1 output (unique rows)
__device__ float g_y2[(size_t)N_PTS * COUT];   // pre-BN layer-2 output (unique rows)
__device__ float g_stats1[2 * CMID];           // weighted sum, sumsq
__device__ float g_stats2[2 * COUT];
__device__ float g_sb1[2 * CMID];              // scale, bias (folded BN)
__device__ float g_sb2[2 * COUT];

// ---------------- packed f32x2 helpers --------------------------------------
__device__ __forceinline__ unsigned long long pack2(float a, float b) {
    unsigned long long r;
    asm("mov.b64 %0, {%1, %2};" : "=l"(r) : "f"(a), "f"(b));
    return r;
}
__device__ __forceinline__ float2 unpack2(unsigned long long v) {
    float2 r;
    asm("mov.b64 {%0, %1}, %2;" : "=f"(r.x), "=f"(r.y) : "l"(v));
    return r;
}
__device__ __forceinline__ void fma2(unsigned long long& d,
                                     unsigned long long a,
                                     unsigned long long b) {
    asm("fma.rn.f32x2 %0, %1, %2, %0;" : "+l"(d) : "l"(a), "l"(b));
}

// ---------------- kernels ----------------------------------------------------
__global__ void zero_kernel() {
    int i = blockIdx.x * blockDim.x + threadIdx.x;
    if (i < N_PTS) g_counts[i] = 0;
    if (i < 2 * CMID) g_stats1[i] = 0.f;
    if (i < 2 * COUT) g_stats2[i] = 0.f;
}

__global__ void count_kernel(const int* __restrict__ idx) {
    int i = blockIdx.x * blockDim.x + threadIdx.x;
    if (i < NK) atomicAdd(&g_counts[idx[i]], 1);
}

// GEMM1: y1[r, 0..63] = feat[r, :] @ W1 + b1 ; weighted stats into g_stats1.
// Block: 256 threads (16x16). Tile: 64 rows x 64 cols. Thread: 4x4.
__global__ __launch_bounds__(256) void gemm1_kernel(const float* __restrict__ feat,
                                                    const float* __restrict__ W1,
                                                    const float* __restrict__ b1) {
    __shared__ float As[64 * 64];   // [row][k]
    __shared__ float Ws[64 * 64];   // [k][col]
    const int tid = threadIdx.x;
    const int tx = tid & 15, ty = tid >> 4;
    const int row0 = blockIdx.x * 64;

    // load W1 (64x64)
#pragma unroll
    for (int it = 0; it < 4; it++) {
        int f = tid + it * 256;
        ((float4*)Ws)[f] = ((const float4*)W1)[f];
    }
    // load A tile
#pragma unroll
    for (int it = 0; it < 4; it++) {
        int f = tid + it * 256;            // [0, 1024)
        int r = f >> 4, k4 = f & 15;
        int grow = row0 + r;
        float4 v = (grow < N_PTS) ? ((const float4*)feat)[grow * 16 + k4]
                                  : make_float4(0.f, 0.f, 0.f, 0.f);
        ((float4*)As)[r * 16 + k4] = v;
    }
    __syncthreads();

    unsigned long long acc[4][2];
#pragma unroll
    for (int i = 0; i < 4; i++) { acc[i][0] = 0ull; acc[i][1] = 0ull; }

#pragma unroll
    for (int kk = 0; kk < 64; kk += 4) {
        float4 a[4];
#pragma unroll
        for (int i = 0; i < 4; i++)
            a[i] = *(const float4*)&As[(ty * 4 + i) * 64 + kk];
#pragma unroll
        for (int kq = 0; kq < 4; kq++) {
            const ulonglong2 bv = *(const ulonglong2*)&Ws[(kk + kq) * 64 + tx * 4];
#pragma unroll
            for (int i = 0; i < 4; i++) {
                float av = (kq == 0) ? a[i].x : (kq == 1) ? a[i].y
                          : (kq == 2) ? a[i].z : a[i].w;
                unsigned long long ad = pack2(av, av);
                fma2(acc[i][0], ad, bv.x);
                fma2(acc[i][1], ad, bv.y);
            }
        }
    }

    const float4 bias = *(const float4*)&b1[tx * 4];
    float ws[4] = {0.f, 0.f, 0.f, 0.f}, wq[4] = {0.f, 0.f, 0.f, 0.f};
#pragma unroll
    for (int i = 0; i < 4; i++) {
        int grow = row0 + ty * 4 + i;
        float2 lo = unpack2(acc[i][0]);
        float2 hi = unpack2(acc[i][1]);
        float y0 = lo.x + bias.x, y1v = lo.y + bias.y;
        float y2v = hi.x + bias.z, y3 = hi.y + bias.w;
        if (grow < N_PTS) {
            *(float4*)&g_y1[(size_t)grow * 64 + tx * 4] = make_float4(y0, y1v, y2v, y3);
            float w = (float)g_counts[grow];
            ws[0] += w * y0;  wq[0] += w * y0 * y0;
            ws[1] += w * y1v; wq[1] += w * y1v * y1v;
            ws[2] += w * y2v; wq[2] += w * y2v * y2v;
            ws[3] += w * y3;  wq[3] += w * y3 * y3;
        }
    }
    __syncthreads();
    float* red = As;  // reuse: 4096 floats, need 2048
#pragma unroll
    for (int j = 0; j < 4; j++) {
        red[ty * 64 + tx * 4 + j] = ws[j];
        red[1024 + ty * 64 + tx * 4 + j] = wq[j];
    }
    __syncthreads();
    if (tid < 64) {
        float s = 0.f, q = 0.f;
#pragma unroll
        for (int t = 0; t < 16; t++) {
            s += red[t * 64 + tid];
            q += red[1024 + t * 64 + tid];
        }
        atomicAdd(&g_stats1[tid], s);
        atomicAdd(&g_stats1[64 + tid], q);
    }
}

__global__ void finalize1_kernel(const float* __restrict__ gamma,
                                 const float* __restrict__ beta) {
    int c = threadIdx.x;
    if (c >= CMID) return;
    float inv_m = 1.0f / (float)NK;
    float mean = g_stats1[c] * inv_m;
    float var = g_stats1[64 + c] * inv_m - mean * mean;
    float sc = gamma[c] * rsqrtf(var + EPSB);
    g_sb1[c] = sc;
    g_sb1[64 + c] = beta[c] - mean * sc;
}

// GEMM2: h = relu(bn1(y1)); y2[r, 0..127] = h @ W2 + b2 ; weighted stats.
// Block: 256 threads (16x16). Tile: 64 rows x 128 cols. Thread: 4x8.
__global__ __launch_bounds__(256) void gemm2_kernel(const float* __restrict__ W2,
                                                    const float* __restrict__ b2) {
    __shared__ float As[64 * 64];    // h tile [row][k]  (16 KB)
    __shared__ float Ws[64 * 128];   // [k][col]         (32 KB)
    const int tid = threadIdx.x;
    const int tx = tid & 15, ty = tid >> 4;
    const int row0 = blockIdx.x * 64;

    // load W2 (64x128)
#pragma unroll
    for (int it = 0; it < 8; it++) {
        int f = tid + it * 256;
        ((float4*)Ws)[f] = ((const float4*)W2)[f];
    }
    // load A tile from g_y1, applying folded BN1 + ReLU on the fly
#pragma unroll
    for (int it = 0; it < 4; it++) {
        int f = tid + it * 256;
        int r = f >> 4, k4 = f & 15;
        int grow = row0 + r;
        float4 v = (grow < N_PTS) ? ((const float4*)g_y1)[grow * 16 + k4]
                                  : make_float4(0.f, 0.f, 0.f, 0.f);
        float4 s = *(const float4*)&g_sb1[k4 * 4];
        float4 bb = *(const float4*)&g_sb1[64 + k4 * 4];
        v.x = fmaxf(fmaf(v.x, s.x, bb.x), 0.f);
        v.y = fmaxf(fmaf(v.y, s.y, bb.y), 0.f);
        v.z = fmaxf(fmaf(v.z, s.z, bb.z), 0.f);
        v.w = fmaxf(fmaf(v.w, s.w, bb.w), 0.f);
        ((float4*)As)[r * 16 + k4] = v;
    }
    __syncthreads();

    unsigned long long acc[4][4];
#pragma unroll
    for (int i = 0; i < 4; i++)
#pragma unroll
        for (int j = 0; j < 4; j++) acc[i][j] = 0ull;

#pragma unroll
    for (int kk = 0; kk < 64; kk += 4) {
        float4 a[4];
#pragma unroll
        for (int i = 0; i < 4; i++)
            a[i] = *(const float4*)&As[(ty * 4 + i) * 64 + kk];
#pragma unroll
        for (int kq = 0; kq < 4; kq++) {
            const ulonglong2 b0 = *(const ulonglong2*)&Ws[(kk + kq) * 128 + tx * 8];
            const ulonglong2 b1v = *(const ulonglong2*)&Ws[(kk + kq) * 128 + tx * 8 + 4];
#pragma unroll
            for (int i = 0; i < 4; i++) {
                float av = (kq == 0) ? a[i].x : (kq == 1) ? a[i].y
                          : (kq == 2) ? a[i].z : a[i].w;
                unsigned long long ad = pack2(av, av);
                fma2(acc[i][0], ad, b0.x);
                fma2(acc[i][1], ad, b0.y);
                fma2(acc[i][2], ad, b1v.x);
                fma2(acc[i][3], ad, b1v.y);
            }
        }
    }

    const float4 biasA = *(const float4*)&b2[tx * 8];
    const float4 biasB = *(const float4*)&b2[tx * 8 + 4];
    float ws[8], wq[8];
#pragma unroll
    for (int j = 0; j < 8; j++) { ws[j] = 0.f; wq[j] = 0.f; }
#pragma unroll
    for (int i = 0; i < 4; i++) {
        int grow = row0 + ty * 4 + i;
        float2 p0 = unpack2(acc[i][0]);
        float2 p1 = unpack2(acc[i][1]);
        float2 p2 = unpack2(acc[i][2]);
        float2 p3 = unpack2(acc[i][3]);
        float y[8];
        y[0] = p0.x + biasA.x; y[1] = p0.y + biasA.y;
        y[2] = p1.x + biasA.z; y[3] = p1.y + biasA.w;
        y[4] = p2.x + biasB.x; y[5] = p2.y + biasB.y;
        y[6] = p3.x + biasB.z; y[7] = p3.y + biasB.w;
        if (grow < N_PTS) {
            *(float4*)&g_y2[(size_t)grow * 128 + tx * 8] =
                make_float4(y[0], y[1], y[2], y[3]);
            *(float4*)&g_y2[(size_t)grow * 128 + tx * 8 + 4] =
                make_float4(y[4], y[5], y[6], y[7]);
            float w = (float)g_counts[grow];
#pragma unroll
            for (int j = 0; j < 8; j++) {
                ws[j] += w * y[j];
                wq[j] += w * y[j] * y[j];
            }
        }
    }
    __syncthreads();
    float* red = As;  // 4096 floats, need 2 * 2048
#pragma unroll
    for (int j = 0; j < 8; j++) {
        red[ty * 128 + tx * 8 + j] = ws[j];
        red[2048 + ty * 128 + tx * 8 + j] = wq[j];
    }
    __syncthreads();
    if (tid < 128) {
        float s = 0.f, q = 0.f;
#pragma unroll
        for (int t = 0; t < 16; t++) {
            s += red[t * 128 + tid];
            q += red[2048 + t * 128 + tid];
        }
        atomicAdd(&g_stats2[tid], s);
        atomicAdd(&g_stats2[128 + tid], q);
    }
}

__global__ void finalize2_kernel(const float* __restrict__ gamma,
                                 const float* __restrict__ beta) {
    int c = threadIdx.x;
    if (c >= COUT) return;
    float inv_m = 1.0f / (float)NK;
    float mean = g_stats2[c] * inv_m;
    float var = g_stats2[128 + c] * inv_m - mean * mean;
    float sc = gamma[c] * rsqrtf(var + EPSB);
    g_sb2[c] = sc;
    g_sb2[128 + c] = beta[c] - mean * sc;
}

// Final gather + max-pool. One warp per output point.
// out[n][c] = relu(s_c * m + b_c), m = (s_c >= 0 ? max_k : min_k) y2[idx[n,k], c]
__global__ __launch_bounds__(256) void gather_max_kernel(
    const int* __restrict__ idx, float* __restrict__ out) {
    int warp = (blockIdx.x * blockDim.x + threadIdx.x) >> 5;
    int lane = threadIdx.x & 31;
    if (warp >= N_PTS) return;

    int myidx = (lane < 16) ? idx[warp * 16 + lane] : 0;

    float4 mx = make_float4(-3.4e38f, -3.4e38f, -3.4e38f, -3.4e38f);
    float4 mn = make_float4(3.4e38f, 3.4e38f, 3.4e38f, 3.4e38f);
#pragma unroll
    for (int k = 0; k < 16; k++) {
        int r = __shfl_sync(0xffffffffu, myidx, k);
        float4 v = *(const float4*)&g_y2[(size_t)r * 128 + lane * 4];
        mx.x = fmaxf(mx.x, v.x); mn.x = fminf(mn.x, v.x);
        mx.y = fmaxf(mx.y, v.y); mn.y = fminf(mn.y, v.y);
        mx.z = fmaxf(mx.z, v.z); mn.z = fminf(mn.z, v.z);
        mx.w = fmaxf(mx.w, v.w); mn.w = fminf(mn.w, v.w);
    }
    float4 s = *(const float4*)&g_sb2[lane * 4];
    float4 b = *(const float4*)&g_sb2[128 + lane * 4];
    float4 o;
    o.x = fmaxf(fmaf(s.x, (s.x >= 0.f ? mx.x : mn.x), b.x), 0.f);
    o.y = fmaxf(fmaf(s.y, (s.y >= 0.f ? mx.y : mn.y), b.y), 0.f);
    o.z = fmaxf(fmaf(s.z, (s.z >= 0.f ? mx.z : mn.z), b.z), 0.f);
    o.w = fmaxf(fmaf(s.w, (s.w >= 0.f ? mx.w : mn.w), b.w), 0.f);
    *(float4*)&out[(size_t)warp * 128 + lane * 4] = o;
}

// ---------------- launch ------------------------------------------------------
extern "C" void kernel_launch(void* const* d_in, const int* in_sizes, int n_in,
                              void* d_out, int out_size) {
    const float* feat = (const float*)d_in[0];
    const int* idx = (const int*)d_in[1];
    const float* W1 = (const float*)d_in[2];
    const float* b1 = (const float*)d_in[3];
    const float* g1 = (const float*)d_in[4];
    const float* be1 = (const float*)d_in[5];
    const float* W2 = (const float*)d_in[6];
    const float* b2 = (const float*)d_in[7];
    const float* g2 = (const float*)d_in[8];
    const float* be2 = (const float*)d_in[9];
    float* out = (float*)d_out;

    zero_kernel<<<(N_PTS + 255) / 256, 256>>>();
    count_kernel<<<(NK + 255) / 256, 256>>>(idx);
    gemm1_kernel<<<(N_PTS + 63) / 64, 256>>>(feat, W1, b1);
    finalize1_kernel<<<1, 64>>>(g1, be1);
    gemm2_kernel<<<(N_PTS + 63) / 64, 256>>>(W2, b2);
    finalize2_kernel<<<1, 128>>>(g2, be2);
    gather_max_kernel<<<(N_PTS * 32 + 255) / 256, 256>>>(idx, out);
}

// round 3
// speedup vs baseline: 1.0452x; 1.0452x over previous
#include <cuda_runtime.h>
#include <cuda_fp16.h>
#include <cstdint>

#define N_PTS 100000
#define KNN   16
#define CIN   64
#define CMID  64
#define COUT  128
#define NK    (N_PTS * KNN)
#define EPSB  1e-5f

// ---------------- scratch (static device memory; no dynamic alloc) ----------
__device__ int    g_counts[N_PTS];
__device__ float  g_y1[(size_t)N_PTS * CMID];   // pre-BN layer-1 output (unique rows)
__device__ float  g_y2[(size_t)N_PTS * COUT];   // pre-BN layer-2 output (unique rows)
__device__ __half g_z[(size_t)N_PTS * COUT];    // relu(bn2(y2)) in fp16
__device__ float  g_stats1[2 * CMID];           // weighted sum, sumsq
__device__ float  g_stats2[2 * COUT];
__device__ float  g_sb1[2 * CMID];              // scale, bias (folded BN)
__device__ float  g_sb2[2 * COUT];

// ---------------- packed f32x2 helpers --------------------------------------
__device__ __forceinline__ unsigned long long pack2(float a, float b) {
    unsigned long long r;
    asm("mov.b64 %0, {%1, %2};" : "=l"(r) : "f"(a), "f"(b));
    return r;
}
__device__ __forceinline__ float2 unpack2(unsigned long long v) {
    float2 r;
    asm("mov.b64 {%0, %1}, %2;" : "=f"(r.x), "=f"(r.y) : "l"(v));
    return r;
}
__device__ __forceinline__ void fma2(unsigned long long& d,
                                     unsigned long long a,
                                     unsigned long long b) {
    asm("fma.rn.f32x2 %0, %1, %2, %0;" : "+l"(d) : "l"(a), "l"(b));
}

// ---------------- kernels ----------------------------------------------------
__global__ void zero_kernel() {
    int i = blockIdx.x * blockDim.x + threadIdx.x;
    if (i < N_PTS) g_counts[i] = 0;
    if (i < 2 * CMID) g_stats1[i] = 0.f;
    if (i < 2 * COUT) g_stats2[i] = 0.f;
}

__global__ void count_kernel(const int* __restrict__ idx) {
    int i = blockIdx.x * blockDim.x + threadIdx.x;
    if (i < NK) atomicAdd(&g_counts[idx[i]], 1);
}

// GEMM1: y1[r, 0..63] = feat[r, :] @ W1 + b1 ; weighted stats into g_stats1.
__global__ __launch_bounds__(256) void gemm1_kernel(const float* __restrict__ feat,
                                                    const float* __restrict__ W1,
                                                    const float* __restrict__ b1) {
    __shared__ float As[64 * 64];   // [row][k]
    __shared__ float Ws[64 * 64];   // [k][col]
    const int tid = threadIdx.x;
    const int tx = tid & 15, ty = tid >> 4;
    const int row0 = blockIdx.x * 64;

#pragma unroll
    for (int it = 0; it < 4; it++) {
        int f = tid + it * 256;
        ((float4*)Ws)[f] = ((const float4*)W1)[f];
    }
#pragma unroll
    for (int it = 0; it < 4; it++) {
        int f = tid + it * 256;
        int r = f >> 4, k4 = f & 15;
        int grow = row0 + r;
        float4 v = (grow < N_PTS) ? ((const float4*)feat)[grow * 16 + k4]
                                  : make_float4(0.f, 0.f, 0.f, 0.f);
        ((float4*)As)[r * 16 + k4] = v;
    }
    __syncthreads();

    unsigned long long acc[4][2];
#pragma unroll
    for (int i = 0; i < 4; i++) { acc[i][0] = 0ull; acc[i][1] = 0ull; }

#pragma unroll
    for (int kk = 0; kk < 64; kk += 4) {
        float4 a[4];
#pragma unroll
        for (int i = 0; i < 4; i++)
            a[i] = *(const float4*)&As[(ty * 4 + i) * 64 + kk];
#pragma unroll
        for (int kq = 0; kq < 4; kq++) {
            const ulonglong2 bv = *(const ulonglong2*)&Ws[(kk + kq) * 64 + tx * 4];
#pragma unroll
            for (int i = 0; i < 4; i++) {
                float av = (kq == 0) ? a[i].x : (kq == 1) ? a[i].y
                          : (kq == 2) ? a[i].z : a[i].w;
                unsigned long long ad = pack2(av, av);
                fma2(acc[i][0], ad, bv.x);
                fma2(acc[i][1], ad, bv.y);
            }
        }
    }

    const float4 bias = *(const float4*)&b1[tx * 4];
    float ws[4] = {0.f, 0.f, 0.f, 0.f}, wq[4] = {0.f, 0.f, 0.f, 0.f};
#pragma unroll
    for (int i = 0; i < 4; i++) {
        int grow = row0 + ty * 4 + i;
        float2 lo = unpack2(acc[i][0]);
        float2 hi = unpack2(acc[i][1]);
        float y0 = lo.x + bias.x, y1v = lo.y + bias.y;
        float y2v = hi.x + bias.z, y3 = hi.y + bias.w;
        if (grow < N_PTS) {
            *(float4*)&g_y1[(size_t)grow * 64 + tx * 4] = make_float4(y0, y1v, y2v, y3);
            float w = (float)g_counts[grow];
            ws[0] += w * y0;  wq[0] += w * y0 * y0;
            ws[1] += w * y1v; wq[1] += w * y1v * y1v;
            ws[2] += w * y2v; wq[2] += w * y2v * y2v;
            ws[3] += w * y3;  wq[3] += w * y3 * y3;
        }
    }
    __syncthreads();
    float* red = As;
#pragma unroll
    for (int j = 0; j < 4; j++) {
        red[ty * 64 + tx * 4 + j] = ws[j];
        red[1024 + ty * 64 + tx * 4 + j] = wq[j];
    }
    __syncthreads();
    if (tid < 64) {
        float s = 0.f, q = 0.f;
#pragma unroll
        for (int t = 0; t < 16; t++) {
            s += red[t * 64 + tid];
            q += red[1024 + t * 64 + tid];
        }
        atomicAdd(&g_stats1[tid], s);
        atomicAdd(&g_stats1[64 + tid], q);
    }
}

__global__ void finalize1_kernel(const float* __restrict__ gamma,
                                 const float* __restrict__ beta) {
    int c = threadIdx.x;
    if (c >= CMID) return;
    float inv_m = 1.0f / (float)NK;
    float mean = g_stats1[c] * inv_m;
    float var = g_stats1[64 + c] * inv_m - mean * mean;
    float sc = gamma[c] * rsqrtf(var + EPSB);
    g_sb1[c] = sc;
    g_sb1[64 + c] = beta[c] - mean * sc;
}

// GEMM2: h = relu(bn1(y1)); y2 = h @ W2 + b2 ; weighted stats.
__global__ __launch_bounds__(256) void gemm2_kernel(const float* __restrict__ W2,
                                                    const float* __restrict__ b2) {
    __shared__ float As[64 * 64];
    __shared__ float Ws[64 * 128];
    const int tid = threadIdx.x;
    const int tx = tid & 15, ty = tid >> 4;
    const int row0 = blockIdx.x * 64;

#pragma unroll
    for (int it = 0; it < 8; it++) {
        int f = tid + it * 256;
        ((float4*)Ws)[f] = ((const float4*)W2)[f];
    }
#pragma unroll
    for (int it = 0; it < 4; it++) {
        int f = tid + it * 256;
        int r = f >> 4, k4 = f & 15;
        int grow = row0 + r;
        float4 v = (grow < N_PTS) ? ((const float4*)g_y1)[grow * 16 + k4]
                                  : make_float4(0.f, 0.f, 0.f, 0.f);
        float4 s = *(const float4*)&g_sb1[k4 * 4];
        float4 bb = *(const float4*)&g_sb1[64 + k4 * 4];
        v.x = fmaxf(fmaf(v.x, s.x, bb.x), 0.f);
        v.y = fmaxf(fmaf(v.y, s.y, bb.y), 0.f);
        v.z = fmaxf(fmaf(v.z, s.z, bb.z), 0.f);
        v.w = fmaxf(fmaf(v.w, s.w, bb.w), 0.f);
        ((float4*)As)[r * 16 + k4] = v;
    }
    __syncthreads();

    unsigned long long acc[4][4];
#pragma unroll
    for (int i = 0; i < 4; i++)
#pragma unroll
        for (int j = 0; j < 4; j++) acc[i][j] = 0ull;

#pragma unroll
    for (int kk = 0; kk < 64; kk += 4) {
        float4 a[4];
#pragma unroll
        for (int i = 0; i < 4; i++)
            a[i] = *(const float4*)&As[(ty * 4 + i) * 64 + kk];
#pragma unroll
        for (int kq = 0; kq < 4; kq++) {
            const ulonglong2 b0 = *(const ulonglong2*)&Ws[(kk + kq) * 128 + tx * 8];
            const ulonglong2 b1v = *(const ulonglong2*)&Ws[(kk + kq) * 128 + tx * 8 + 4];
#pragma unroll
            for (int i = 0; i < 4; i++) {
                float av = (kq == 0) ? a[i].x : (kq == 1) ? a[i].y
                          : (kq == 2) ? a[i].z : a[i].w;
                unsigned long long ad = pack2(av, av);
                fma2(acc[i][0], ad, b0.x);
                fma2(acc[i][1], ad, b0.y);
                fma2(acc[i][2], ad, b1v.x);
                fma2(acc[i][3], ad, b1v.y);
            }
        }
    }

    const float4 biasA = *(const float4*)&b2[tx * 8];
    const float4 biasB = *(const float4*)&b2[tx * 8 + 4];
    float ws[8], wq[8];
#pragma unroll
    for (int j = 0; j < 8; j++) { ws[j] = 0.f; wq[j] = 0.f; }
#pragma unroll
    for (int i = 0; i < 4; i++) {
        int grow = row0 + ty * 4 + i;
        float2 p0 = unpack2(acc[i][0]);
        float2 p1 = unpack2(acc[i][1]);
        float2 p2 = unpack2(acc[i][2]);
        float2 p3 = unpack2(acc[i][3]);
        float y[8];
        y[0] = p0.x + biasA.x; y[1] = p0.y + biasA.y;
        y[2] = p1.x + biasA.z; y[3] = p1.y + biasA.w;
        y[4] = p2.x + biasB.x; y[5] = p2.y + biasB.y;
        y[6] = p3.x + biasB.z; y[7] = p3.y + biasB.w;
        if (grow < N_PTS) {
            *(float4*)&g_y2[(size_t)grow * 128 + tx * 8] =
                make_float4(y[0], y[1], y[2], y[3]);
            *(float4*)&g_y2[(size_t)grow * 128 + tx * 8 + 4] =
                make_float4(y[4], y[5], y[6], y[7]);
            float w = (float)g_counts[grow];
#pragma unroll
            for (int j = 0; j < 8; j++) {
                ws[j] += w * y[j];
                wq[j] += w * y[j] * y[j];
            }
        }
    }
    __syncthreads();
    float* red = As;
#pragma unroll
    for (int j = 0; j < 8; j++) {
        red[ty * 128 + tx * 8 + j] = ws[j];
        red[2048 + ty * 128 + tx * 8 + j] = wq[j];
    }
    __syncthreads();
    if (tid < 128) {
        float s = 0.f, q = 0.f;
#pragma unroll
        for (int t = 0; t < 16; t++) {
            s += red[t * 128 + tid];
            q += red[2048 + t * 128 + tid];
        }
        atomicAdd(&g_stats2[tid], s);
        atomicAdd(&g_stats2[128 + tid], q);
    }
}

__global__ void finalize2_kernel(const float* __restrict__ gamma,
                                 const float* __restrict__ beta) {
    int c = threadIdx.x;
    if (c >= COUT) return;
    float inv_m = 1.0f / (float)NK;
    float mean = g_stats2[c] * inv_m;
    float var = g_stats2[128 + c] * inv_m - mean * mean;
    float sc = gamma[c] * rsqrtf(var + EPSB);
    g_sb2[c] = sc;
    g_sb2[128 + c] = beta[c] - mean * sc;
}

// Transform: z = relu(bn2(y2)) computed in fp32, stored fp16.
// One thread per 8 channels: N_PTS*16 threads.
__global__ __launch_bounds__(256) void transform_kernel() {
    int t = blockIdx.x * blockDim.x + threadIdx.x;
    if (t >= N_PTS * 16) return;
    int p = t >> 4, g = t & 15;
    size_t off = (size_t)p * 128 + g * 8;
    float4 v0 = *(const float4*)&g_y2[off];
    float4 v1 = *(const float4*)&g_y2[off + 4];
    float4 s0 = *(const float4*)&g_sb2[g * 8];
    float4 s1 = *(const float4*)&g_sb2[g * 8 + 4];
    float4 b0 = *(const float4*)&g_sb2[128 + g * 8];
    float4 b1 = *(const float4*)&g_sb2[128 + g * 8 + 4];
    float z[8];
    z[0] = fmaxf(fmaf(v0.x, s0.x, b0.x), 0.f);
    z[1] = fmaxf(fmaf(v0.y, s0.y, b0.y), 0.f);
    z[2] = fmaxf(fmaf(v0.z, s0.z, b0.z), 0.f);
    z[3] = fmaxf(fmaf(v0.w, s0.w, b0.w), 0.f);
    z[4] = fmaxf(fmaf(v1.x, s1.x, b1.x), 0.f);
    z[5] = fmaxf(fmaf(v1.y, s1.y, b1.y), 0.f);
    z[6] = fmaxf(fmaf(v1.z, s1.z, b1.z), 0.f);
    z[7] = fmaxf(fmaf(v1.w, s1.w, b1.w), 0.f);
    __half2 h[4];
#pragma unroll
    for (int j = 0; j < 4; j++)
        h[j] = __floats2half2_rn(z[2 * j], z[2 * j + 1]);
    *(uint4*)&g_z[off] = *(uint4*)h;
}

// Final gather + max-pool over fp16 table. One warp handles TWO points:
// lanes 0-15 -> point 2w, lanes 16-31 -> point 2w+1. Each lane: 8 channels (16B).
__global__ __launch_bounds__(256) void gather_max_kernel(
    const int* __restrict__ idx, float* __restrict__ out) {
    int warp = (blockIdx.x * blockDim.x + threadIdx.x) >> 5;
    int lane = threadIdx.x & 31;
    int p = warp * 2 + (lane >> 4);          // this half-warp's point
    if (p >= N_PTS) return;
    int half_lane = lane & 15;

    // lane l holds idx[point(l)][l&15]
    int myidx = idx[p * 16 + half_lane];

    __half2 mx[4];
#pragma unroll
    for (int j = 0; j < 4; j++) mx[j] = __floats2half2_rn(0.f, 0.f);  // values >= 0

#pragma unroll
    for (int k = 0; k < 16; k++) {
        // broadcast k-th neighbor of each half-warp's point
        int r = __shfl_sync(0xffffffffu, myidx, (lane & 16) + k);
        uint4 raw = *(const uint4*)&g_z[(size_t)r * 128 + half_lane * 8];
        __half2 v[4];
        *(uint4*)v = raw;
        mx[0] = __hmax2(mx[0], v[0]);
        mx[1] = __hmax2(mx[1], v[1]);
        mx[2] = __hmax2(mx[2], v[2]);
        mx[3] = __hmax2(mx[3], v[3]);
    }

    size_t off = (size_t)p * 128 + half_lane * 8;
    float2 f0 = __half22float2(mx[0]);
    float2 f1 = __half22float2(mx[1]);
    float2 f2 = __half22float2(mx[2]);
    float2 f3 = __half22float2(mx[3]);
    *(float4*)&out[off]     = make_float4(f0.x, f0.y, f1.x, f1.y);
    *(float4*)&out[off + 4] = make_float4(f2.x, f2.y, f3.x, f3.y);
}

// ---------------- launch ------------------------------------------------------
extern "C" void kernel_launch(void* const* d_in, const int* in_sizes, int n_in,
                              void* d_out, int out_size) {
    const float* feat = (const float*)d_in[0];
    const int* idx = (const int*)d_in[1];
    const float* W1 = (const float*)d_in[2];
    const float* b1 = (const float*)d_in[3];
    const float* g1 = (const float*)d_in[4];
    const float* be1 = (const float*)d_in[5];
    const float* W2 = (const float*)d_in[6];
    const float* b2 = (const float*)d_in[7];
    const float* g2 = (const float*)d_in[8];
    const float* be2 = (const float*)d_in[9];
    float* out = (float*)d_out;

    zero_kernel<<<(N_PTS + 255) / 256, 256>>>();
    count_kernel<<<(NK + 255) / 256, 256>>>(idx);
    gemm1_kernel<<<(N_PTS + 63) / 64, 256>>>(feat, W1, b1);
    finalize1_kernel<<<1, 64>>>(g1, be1);
    gemm2_kernel<<<(N_PTS + 63) / 64, 256>>>(W2, b2);
    finalize2_kernel<<<1, 128>>>(g2, be2);
    transform_kernel<<<(N_PTS * 16 + 255) / 256, 256>>>();
    // 2 points per warp -> N_PTS/2 warps -> *16 threads per point
    gather_max_kernel<<<(N_PTS * 16 + 255) / 256, 256>>>(idx, out);
}